// round 15
// baseline (speedup 1.0000x reference)
#include <cuda_runtime.h>
#include <cuda_bf16.h>
#include <math.h>
#include <stdint.h>

// ---------------- problem constants ----------------
constexpr int NN  = 65536;      // nodes
constexpr int DD  = 256;        // hidden
constexpr int EE  = 524288;     // edges
constexpr int LL  = 4;          // layers
constexpr int GG  = 512;        // graphs
constexpr int NPG = 128;        // nodes per graph
constexpr int HH  = 8;          // heads
constexpr int DHH = 32;         // head dim
constexpr int WW  = 20;         // walk length (pe dim)
constexpr int AV  = 128;        // atom vocab
constexpr int BV  = 8;          // bond vocab
constexpr int FF  = 512;        // mlp hidden

// ---------------- scratch (device globals; no alloc allowed) ----------------
__device__ float g_h   [NN * DD];
__device__ float g_z   [NN * DD];
__device__ float g_t1  [NN * DD];
__device__ float g_hl  [NN * DD];
__device__ float g_qkv [NN * 3 * DD];
__device__ float g_sum [2][DD];      // double-buffered BN stats
__device__ float g_ss  [2][DD];

// bf16 hi/lo activation buffers
__device__ unsigned short g_xh [NN * DD];   // z / t2 / attn / comb (sequential reuse)
__device__ unsigned short g_xl [NN * DD];
__device__ unsigned short g_hsh[NN * DD];   // h split (for qkv GEMM)
__device__ unsigned short g_hsl[NN * DD];
__device__ unsigned short g_fsh[NN * FF];   // ff split
__device__ unsigned short g_fsl[NN * FF];

// transposed bf16 hi/lo weights: per layer 655360 elems
// offsets: w1=0, w2=65536, qkv=131072, wo=327680, mlp1=393216, mlp2=524288
constexpr long WL_STRIDE = 655360;
__device__ unsigned short g_wh[LL * WL_STRIDE];
__device__ unsigned short g_wl[LL * WL_STRIDE];

// =====================================================================
// helpers
// =====================================================================
__device__ __forceinline__ uint32_t smem_u32(const void* p) {
    uint32_t a;
    asm("{ .reg .u64 t; cvta.to.shared.u64 t, %1; cvt.u32.u64 %0, t; }" : "=r"(a) : "l"(p));
    return a;
}

#define CPA16(dst, src) \
    asm volatile("cp.async.cg.shared.global [%0], [%1], 16;" \
        :: "r"(dst), "l"(src) : "memory")
#define CPA_COMMIT() asm volatile("cp.async.commit_group;" ::: "memory")
#define CPA_WAIT_ALL() asm volatile("cp.async.wait_group 0;" ::: "memory")

__device__ __forceinline__ void ldsm_x4(uint32_t* r, uint32_t addr) {
    asm volatile("ldmatrix.sync.aligned.m8n8.x4.shared.b16 {%0,%1,%2,%3}, [%4];"
        : "=r"(r[0]), "=r"(r[1]), "=r"(r[2]), "=r"(r[3]) : "r"(addr));
}
__device__ __forceinline__ void ldsm_x2(uint32_t* r, uint32_t addr) {
    asm volatile("ldmatrix.sync.aligned.m8n8.x2.shared.b16 {%0,%1}, [%2];"
        : "=r"(r[0]), "=r"(r[1]) : "r"(addr));
}
__device__ __forceinline__ void mma16816(float* c, const uint32_t* a, const uint32_t* b) {
    asm volatile(
        "mma.sync.aligned.m16n8k16.row.col.f32.bf16.bf16.f32 "
        "{%0,%1,%2,%3}, {%4,%5,%6,%7}, {%8,%9}, {%0,%1,%2,%3};"
        : "+f"(c[0]), "+f"(c[1]), "+f"(c[2]), "+f"(c[3])
        : "r"(a[0]), "r"(a[1]), "r"(a[2]), "r"(a[3]), "r"(b[0]), "r"(b[1]));
}

// split fp32 -> (hi, lo) bf16 pair packed helpers
__device__ __forceinline__ void split2(float a, float b, uint32_t& hi, uint32_t& lo) {
    __nv_bfloat16 h0 = __float2bfloat16_rn(a);
    __nv_bfloat16 h1 = __float2bfloat16_rn(b);
    float r0 = a - __bfloat162float(h0);
    float r1 = b - __bfloat162float(h1);
    __nv_bfloat16 l0 = __float2bfloat16_rn(r0);
    __nv_bfloat16 l1 = __float2bfloat16_rn(r1);
    hi = ((uint32_t)__bfloat16_as_ushort(h1) << 16) | __bfloat16_as_ushort(h0);
    lo = ((uint32_t)__bfloat16_as_ushort(l1) << 16) | __bfloat16_as_ushort(l0);
}

// =====================================================================
// weight prep (single launch): W[K,N] fp32 -> Wt[N,K] bf16 hi/lo
// also zeroes both BN stat buffers (block 0).
// =====================================================================
__global__ void k_wprep_all(const float* __restrict__ gw1, const float* __restrict__ gw2,
                            const float* __restrict__ wqkv, const float* __restrict__ wo,
                            const float* __restrict__ mw1, const float* __restrict__ mw2) {
    if (blockIdx.x == 0) {
        for (int i = threadIdx.x; i < 2 * DD; i += 256) {
            g_sum[i / DD][i % DD] = 0.f;
            g_ss [i / DD][i % DD] = 0.f;
        }
    }
    long idx = (long)blockIdx.x * 256 + threadIdx.x;
    if (idx >= (long)LL * WL_STRIDE) return;
    int l = (int)(idx / WL_STRIDE);
    int r = (int)(idx % WL_STRIDE);
    const float* W; int K, N; int seg; long off;
    if      (r < 65536)  { W = gw1  + (long)l * 65536;  K = 256; N = 256; seg = r;          off = 0; }
    else if (r < 131072) { W = gw2  + (long)l * 65536;  K = 256; N = 256; seg = r - 65536;  off = 65536; }
    else if (r < 327680) { W = wqkv + (long)l * 196608; K = 256; N = 768; seg = r - 131072; off = 131072; }
    else if (r < 393216) { W = wo   + (long)l * 65536;  K = 256; N = 256; seg = r - 327680; off = 327680; }
    else if (r < 524288) { W = mw1  + (long)l * 131072; K = 256; N = 512; seg = r - 393216; off = 393216; }
    else                 { W = mw2  + (long)l * 131072; K = 512; N = 256; seg = r - 524288; off = 524288; }
    int k = seg / N, n = seg % N;
    float v = W[seg];
    __nv_bfloat16 h = __float2bfloat16_rn(v);
    float lo = v - __bfloat162float(h);
    __nv_bfloat16 lw = __float2bfloat16_rn(lo);
    g_wh[(long)l * WL_STRIDE + off + (long)n * K + k] = __bfloat16_as_ushort(h);
    g_wl[(long)l * WL_STRIDE + off + (long)n * K + k] = __bfloat16_as_ushort(lw);
}

// =====================================================================
// activation convert: X fp32 [n] -> Xh/Xl bf16
// =====================================================================
__global__ void k_acvt(const float* __restrict__ X,
                       unsigned short* __restrict__ Xh, unsigned short* __restrict__ Xl) {
    long i4 = ((long)blockIdx.x * 256 + threadIdx.x) * 4;
    float4 v = *(const float4*)(X + i4);
    uint32_t h0, l0, h1, l1;
    split2(v.x, v.y, h0, l0);
    split2(v.z, v.w, h1, l1);
    *(uint2*)(Xh + i4) = make_uint2(h0, h1);
    *(uint2*)(Xl + i4) = make_uint2(l0, l1);
}

// =====================================================================
// mma.sync GEMM: C[M,Nn] = A[M,K] @ B[K,Nn] + bias (+relu) (+res)
//                (+BN stats) ; output fp32 OR bf16 hi/lo split
// A and B both pre-split bf16 hi/lo. 3 products: hh + hl + lh.
// CTA tile 128x128, warp tile 32x64, K-chunk 32, 256 threads, occ 2.
// 2-stage cp.async double buffer; one syncthreads per chunk.
// smem rows 64B data + 16B pad = 80B -> conflict-free ldmatrix.
// =====================================================================
constexpr int ROWB  = 80;
constexpr int MAT   = 128 * ROWB;       // 10240
constexpr int SA_H  = 0;
constexpr int SA_L  = MAT;
constexpr int SB_H  = 2 * MAT;
constexpr int SB_L  = 3 * MAT;
constexpr int STAGE = 4 * MAT;          // 40960
constexpr int SM_TOT = 2 * STAGE;       // 81920

__global__ void __launch_bounds__(256, 2) k_tgemm(
    const unsigned short* __restrict__ Ah, const unsigned short* __restrict__ Al,
    const unsigned short* __restrict__ Bh, const unsigned short* __restrict__ Bl,
    const float* __restrict__ bias, const float* __restrict__ res,
    float* __restrict__ Cf,
    unsigned short* __restrict__ Ch, unsigned short* __restrict__ Cl,
    int Nn, int K, int relu, int do_stats, int par)
{
    extern __shared__ char smbuf[];
    uint32_t sb = smem_u32(smbuf);
    int tid = threadIdx.x, wid = tid >> 5, lane = tid & 31;
    int m0 = blockIdx.y * 128;
    int n0 = blockIdx.x * 128;
    const int wm = (wid & 3) * 32;
    const int wn = (wid >> 2) * 64;

    float acc[2][8][4];
#pragma unroll
    for (int i = 0; i < 2; i++)
#pragma unroll
        for (int j = 0; j < 8; j++)
#pragma unroll
            for (int q = 0; q < 4; q++) acc[i][j][q] = 0.f;

    // loader mapping: 2 threads per row, 16 elems (32B) each
    const int lr = tid >> 1;
    const int le = (tid & 1) * 16;       // elem offset in chunk
    const unsigned short* ah = Ah + (long)(m0 + lr) * K + le;
    const unsigned short* al = Al + (long)(m0 + lr) * K + le;
    const unsigned short* bh = Bh + (long)(n0 + lr) * K + le;
    const unsigned short* bl = Bl + (long)(n0 + lr) * K + le;
    const uint32_t sd = sb + (uint32_t)(lr * ROWB + (tid & 1) * 32);

    const int nch = K >> 5;

    // ldmatrix per-lane patterns
    const int a_row = lane & 15;
    const int a_cb  = (lane >> 4) * 16;
    const int b_row = lane & 7;
    const int b_cb  = ((lane >> 3) & 1) * 16;

    // prologue: chunk 0 -> stage 0
    {
        CPA16(sd + SA_H, ah); CPA16(sd + SA_H + 16, ah + 8);
        CPA16(sd + SA_L, al); CPA16(sd + SA_L + 16, al + 8);
        CPA16(sd + SB_H, bh); CPA16(sd + SB_H + 16, bh + 8);
        CPA16(sd + SB_L, bl); CPA16(sd + SB_L + 16, bl + 8);
        CPA_COMMIT();
    }

    for (int c = 0; c < nch; c++) {
        const uint32_t sbp = sb + (uint32_t)((c & 1) * STAGE);
        CPA_WAIT_ALL();      // chunk c landed
        __syncthreads();     // visible to all; stage (c+1)&1 free (consumed at c-1)
        if (c + 1 < nch) {
            const int kc = (c + 1) * 32;
            const uint32_t nd = sd + (uint32_t)(((c + 1) & 1) * STAGE);
            CPA16(nd + SA_H, ah + kc); CPA16(nd + SA_H + 16, ah + kc + 8);
            CPA16(nd + SA_L, al + kc); CPA16(nd + SA_L + 16, al + kc + 8);
            CPA16(nd + SB_H, bh + kc); CPA16(nd + SB_H + 16, bh + kc + 8);
            CPA16(nd + SB_L, bl + kc); CPA16(nd + SB_L + 16, bl + kc + 8);
            CPA_COMMIT();
        }
        // ---- MMA chunk c: 2 k-steps x (2 mf x 8 nf) x 3 products ----
#pragma unroll
        for (int ks = 0; ks < 2; ks++) {
            uint32_t ahf[2][4], alf[2][4];
#pragma unroll
            for (int mf = 0; mf < 2; mf++) {
                uint32_t aaddr = sbp + SA_H +
                    (uint32_t)((wm + mf * 16 + a_row) * ROWB + ks * 32 + a_cb);
                ldsm_x4(ahf[mf], aaddr);
                ldsm_x4(alf[mf], aaddr + MAT);
            }
#pragma unroll
            for (int nf = 0; nf < 8; nf++) {
                uint32_t baddr = sbp + SB_H +
                    (uint32_t)((wn + nf * 8 + b_row) * ROWB + ks * 32 + b_cb);
                uint32_t bh2[2], bl2[2];
                ldsm_x2(bh2, baddr);
                ldsm_x2(bl2, baddr + MAT);
#pragma unroll
                for (int mf = 0; mf < 2; mf++) {
                    mma16816(acc[mf][nf], ahf[mf], bh2);
                    mma16816(acc[mf][nf], ahf[mf], bl2);
                    mma16816(acc[mf][nf], alf[mf], bh2);
                }
            }
        }
    }

    // ---- epilogue ----
    float s[16], q2[16];
#pragma unroll
    for (int i = 0; i < 16; i++) { s[i] = 0.f; q2[i] = 0.f; }

#pragma unroll
    for (int mf = 0; mf < 2; mf++) {
        int row0 = m0 + wm + mf * 16 + (lane >> 2);
#pragma unroll
        for (int nf = 0; nf < 8; nf++) {
            int col = n0 + wn + nf * 8 + (lane & 3) * 2;
            float2 bv = *(const float2*)(bias + col);
            float c0 = acc[mf][nf][0] + bv.x;
            float c1 = acc[mf][nf][1] + bv.y;
            float c2 = acc[mf][nf][2] + bv.x;
            float c3 = acc[mf][nf][3] + bv.y;
            if (relu) {
                c0 = fmaxf(c0, 0.f); c1 = fmaxf(c1, 0.f);
                c2 = fmaxf(c2, 0.f); c3 = fmaxf(c3, 0.f);
            }
            if (res) {
                float2 r0 = *(const float2*)(res + (long)row0 * Nn + col);
                float2 r1 = *(const float2*)(res + (long)(row0 + 8) * Nn + col);
                c0 += r0.x; c1 += r0.y; c2 += r1.x; c3 += r1.y;
            }
            if (Cf) {
                *(float2*)(Cf + (long)row0 * Nn + col) = make_float2(c0, c1);
                *(float2*)(Cf + (long)(row0 + 8) * Nn + col) = make_float2(c2, c3);
            }
            if (Ch) {
                uint32_t h0, l0, h1, l1;
                split2(c0, c1, h0, l0);
                split2(c2, c3, h1, l1);
                *(uint32_t*)(Ch + (long)row0 * Nn + col) = h0;
                *(uint32_t*)(Cl + (long)row0 * Nn + col) = l0;
                *(uint32_t*)(Ch + (long)(row0 + 8) * Nn + col) = h1;
                *(uint32_t*)(Cl + (long)(row0 + 8) * Nn + col) = l1;
            }
            if (do_stats) {
                s[nf * 2 + 0]  += c0 + c2;
                s[nf * 2 + 1]  += c1 + c3;
                q2[nf * 2 + 0] += c0 * c0 + c2 * c2;
                q2[nf * 2 + 1] += c1 * c1 + c3 * c3;
            }
        }
    }
    if (do_stats) {
#pragma unroll
        for (int i = 0; i < 16; i++) {
#pragma unroll
            for (int m = 4; m <= 16; m <<= 1) {
                s[i]  += __shfl_xor_sync(0xffffffffu, s[i],  m);
                q2[i] += __shfl_xor_sync(0xffffffffu, q2[i], m);
            }
        }
        if ((lane >> 2) == 0) {
#pragma unroll
            for (int nf = 0; nf < 8; nf++) {
                int col = n0 + wn + nf * 8 + lane * 2;
                atomicAdd(&g_sum[par][col],     s[nf * 2 + 0]);
                atomicAdd(&g_sum[par][col + 1], s[nf * 2 + 1]);
                atomicAdd(&g_ss[par][col],      q2[nf * 2 + 0]);
                atomicAdd(&g_ss[par][col + 1],  q2[nf * 2 + 1]);
            }
        }
    }
}

// =====================================================================
// non-GEMM kernels
// =====================================================================
__global__ void k_encode(const int* __restrict__ x, const float* __restrict__ pe,
                         const float* __restrict__ atom, const float* __restrict__ pe_w,
                         const float* __restrict__ pe_b) {
    int n = blockIdx.x;
    int d = threadIdx.x * 4;
    __shared__ int   xs[9];
    __shared__ float ps[WW];
    if (threadIdx.x < 9) xs[threadIdx.x] = x[n * 9 + threadIdx.x];
    if (threadIdx.x >= 32 && threadIdx.x < 32 + WW) ps[threadIdx.x - 32] = pe[n * WW + (threadIdx.x - 32)];
    __syncthreads();
    float4 acc = *(const float4*)(pe_b + d);
#pragma unroll
    for (int c = 0; c < 9; c++) {
        float4 v = *(const float4*)(atom + ((long)(c * AV + xs[c]) * DD + d));
        acc.x += v.x; acc.y += v.y; acc.z += v.z; acc.w += v.w;
    }
#pragma unroll
    for (int w = 0; w < WW; w++) {
        float p = ps[w];
        float4 v = *(const float4*)(pe_w + (long)w * DD + d);
        acc.x = fmaf(p, v.x, acc.x); acc.y = fmaf(p, v.y, acc.y);
        acc.z = fmaf(p, v.z, acc.z); acc.w = fmaf(p, v.w, acc.w);
    }
    long o = (long)n * DD + d;
    *(float4*)(g_h + o) = acc;
    uint32_t h0, l0, h1, l1;
    split2(acc.x, acc.y, h0, l0);
    split2(acc.z, acc.w, h1, l1);
    *(uint2*)(g_hsh + o) = make_uint2(h0, h1);
    *(uint2*)(g_hsl + o) = make_uint2(l0, l1);
}

__global__ void k_scatter(const int* __restrict__ ei, const int* __restrict__ eattr,
                          const float* __restrict__ bond) {
    int le = threadIdx.x >> 6;
    int d  = (threadIdx.x & 63) * 4;
    long e = (long)blockIdx.x * 4 + le;
    int src = ei[e];
    int dst = ei[(long)EE + e];
    int a0 = eattr[e * 3 + 0], a1 = eattr[e * 3 + 1], a2 = eattr[e * 3 + 2];
    float4 hv = *(const float4*)(g_h + (long)src * DD + d);
    float4 b0 = *(const float4*)(bond + (long)(0 * BV + a0) * DD + d);
    float4 b1 = *(const float4*)(bond + (long)(1 * BV + a1) * DD + d);
    float4 b2 = *(const float4*)(bond + (long)(2 * BV + a2) * DD + d);
    float m0 = fmaxf(hv.x + b0.x + b1.x + b2.x, 0.f);
    float m1 = fmaxf(hv.y + b0.y + b1.y + b2.y, 0.f);
    float m2 = fmaxf(hv.z + b0.z + b1.z + b2.z, 0.f);
    float m3 = fmaxf(hv.w + b0.w + b1.w + b2.w, 0.f);
    float* zp = g_z + (long)dst * DD + d;
    atomicAdd(zp + 0, m0); atomicAdd(zp + 1, m1);
    atomicAdd(zp + 2, m2); atomicAdd(zp + 3, m3);
}

// BatchNorm apply. Outputs: optional fp32 Ofp, optional split (Oh,Ol).
// Optional post-bn residual add (radd). Zeroes stats[par^1].
__global__ void k_bn(const float* __restrict__ A,
                     const float* __restrict__ gma, const float* __restrict__ bta,
                     float* __restrict__ Ofp,
                     unsigned short* __restrict__ Oh, unsigned short* __restrict__ Ol,
                     const float* __restrict__ radd, int relu, int par) {
    long i = ((long)blockIdx.x * 256 + threadIdx.x) * 2;
    int d = (int)(i & (DD - 1));
    float2 mu2 = *(const float2*)(&g_sum[par][d]);
    float2 ss2 = *(const float2*)(&g_ss[par][d]);
    float2 gm  = *(const float2*)(gma + d);
    float2 bt  = *(const float2*)(bta + d);
    float2 va  = *(const float2*)(A + i);
    float mu0 = mu2.x * (1.f / NN), mu1 = mu2.y * (1.f / NN);
    float v0 = (va.x - mu0) * rsqrtf(ss2.x * (1.f / NN) - mu0 * mu0 + 1e-5f) * gm.x + bt.x;
    float v1 = (va.y - mu1) * rsqrtf(ss2.y * (1.f / NN) - mu1 * mu1 + 1e-5f) * gm.y + bt.y;
    if (relu) { v0 = fmaxf(v0, 0.f); v1 = fmaxf(v1, 0.f); }
    if (radd) {
        float2 r = *(const float2*)(radd + i);
        v0 += r.x; v1 += r.y;
    }
    if (Ofp) *(float2*)(Ofp + i) = make_float2(v0, v1);
    if (Oh) {
        uint32_t h0, l0;
        split2(v0, v1, h0, l0);
        *(uint32_t*)(Oh + i) = h0;
        *(uint32_t*)(Ol + i) = l0;
    }
    if (blockIdx.x == 0 && threadIdx.x < DD / 2) {
        *(float2*)(&g_sum[par ^ 1][threadIdx.x * 2]) = make_float2(0.f, 0.f);
        *(float2*)(&g_ss [par ^ 1][threadIdx.x * 2]) = make_float2(0.f, 0.f);
    }
}

constexpr int ATTN_SMEM = (2 * NPG * 33 + NPG * 129) * 4;
__global__ void k_attention() {
    extern __shared__ float sm[];
    float* Ks = sm;
    float* Vs = Ks + NPG * 33;
    float* Ss = Vs + NPG * 33;
    int head = blockIdx.x, g = blockIdx.y;
    int i = threadIdx.x;
    const float* base = g_qkv + (long)(g * NPG + i) * (3 * DD);

    float q[DHH];
#pragma unroll
    for (int k = 0; k < DHH; k++) {
        q[k] = base[head * DHH + k];
        Ks[i * 33 + k] = base[DD + head * DHH + k];
        Vs[i * 33 + k] = base[2 * DD + head * DHH + k];
    }
    __syncthreads();

    const float scale = 0.17677669529663688f;
    float mx = -1e30f;
#pragma unroll 4
    for (int j = 0; j < NPG; j++) {
        float sv = 0.f;
#pragma unroll
        for (int k = 0; k < DHH; k++) sv = fmaf(q[k], Ks[j * 33 + k], sv);
        sv *= scale;
        Ss[i * 129 + j] = sv;
        mx = fmaxf(mx, sv);
    }
    float denom = 0.f;
#pragma unroll 4
    for (int j = 0; j < NPG; j++) {
        float p = __expf(Ss[i * 129 + j] - mx);
        Ss[i * 129 + j] = p;
        denom += p;
    }
    float inv = 1.f / denom;
    float o[DHH];
#pragma unroll
    for (int k = 0; k < DHH; k++) o[k] = 0.f;
#pragma unroll 4
    for (int j = 0; j < NPG; j++) {
        float p = Ss[i * 129 + j];
#pragma unroll
        for (int k = 0; k < DHH; k++) o[k] = fmaf(p, Vs[j * 33 + k], o[k]);
    }
    // write split bf16 hi/lo (attn only feeds the wo GEMM)
    long ob = (long)(g * NPG + i) * DD + head * DHH;
#pragma unroll
    for (int k = 0; k < DHH; k += 2) {
        uint32_t h0, l0;
        split2(o[k] * inv, o[k + 1] * inv, h0, l0);
        *(uint32_t*)(g_xh + ob + k) = h0;
        *(uint32_t*)(g_xl + ob + k) = l0;
    }
}

__global__ void k_pool(float* __restrict__ out) {
    int g = blockIdx.x, d = threadIdx.x;
    float s = 0.f;
    for (int i = 0; i < NPG; i++) s += g_h[(long)(g * NPG + i) * DD + d];
    out[g * DD + d] = s;
}

// =====================================================================
// host orchestration
// =====================================================================
static void tgemm(const unsigned short* Ah, const unsigned short* Al,
                  const unsigned short* Bh, const unsigned short* Bl,
                  const float* bias, const float* res,
                  float* Cf, unsigned short* Ch, unsigned short* Cl,
                  int Nn, int K, int relu, int do_stats, int par) {
    dim3 grid(Nn / 128, NN / 128);
    k_tgemm<<<grid, 256, SM_TOT>>>(Ah, Al, Bh, Bl, bias, res, Cf, Ch, Cl,
                                   Nn, K, relu, do_stats, par);
}

extern "C" void kernel_launch(void* const* d_in, const int* in_sizes, int n_in,
                              void* d_out, int out_size) {
    const int*   x     = (const int*)d_in[0];
    const int*   ei    = (const int*)d_in[1];
    const int*   eattr = (const int*)d_in[2];
    const float* pe    = (const float*)d_in[4];
    const float* atom  = (const float*)d_in[5];
    const float* bond  = (const float*)d_in[6];
    const float* pe_w  = (const float*)d_in[7];
    const float* pe_b  = (const float*)d_in[8];
    const float* gw1   = (const float*)d_in[9];
    const float* gb1   = (const float*)d_in[10];
    const float* gg1   = (const float*)d_in[11];
    const float* gbe1  = (const float*)d_in[12];
    const float* gw2   = (const float*)d_in[13];
    const float* gb2   = (const float*)d_in[14];
    const float* wqkv  = (const float*)d_in[15];
    const float* bqkv  = (const float*)d_in[16];
    const float* wo    = (const float*)d_in[17];
    const float* bo    = (const float*)d_in[18];
    const float* n1g   = (const float*)d_in[19];
    const float* n1b   = (const float*)d_in[20];
    const float* n2g   = (const float*)d_in[21];
    const float* n2b   = (const float*)d_in[22];
    const float* n3g   = (const float*)d_in[23];
    const float* n3b   = (const float*)d_in[24];
    const float* mw1   = (const float*)d_in[25];
    const float* mb1   = (const float*)d_in[26];
    const float* mw2   = (const float*)d_in[27];
    const float* mb2   = (const float*)d_in[28];

    float *h, *z, *t1, *hl, *qkv;
    unsigned short *wh, *wl, *xh, *xl, *hsh, *hsl, *fsh, *fsl;
    cudaGetSymbolAddress((void**)&h,    g_h);
    cudaGetSymbolAddress((void**)&z,    g_z);
    cudaGetSymbolAddress((void**)&t1,   g_t1);
    cudaGetSymbolAddress((void**)&hl,   g_hl);
    cudaGetSymbolAddress((void**)&qkv,  g_qkv);
    cudaGetSymbolAddress((void**)&wh,   g_wh);
    cudaGetSymbolAddress((void**)&wl,   g_wl);
    cudaGetSymbolAddress((void**)&xh,   g_xh);
    cudaGetSymbolAddress((void**)&xl,   g_xl);
    cudaGetSymbolAddress((void**)&hsh,  g_hsh);
    cudaGetSymbolAddress((void**)&hsl,  g_hsl);
    cudaGetSymbolAddress((void**)&fsh,  g_fsh);
    cudaGetSymbolAddress((void**)&fsl,  g_fsl);

    cudaFuncSetAttribute(k_attention, cudaFuncAttributeMaxDynamicSharedMemorySize, ATTN_SMEM);
    cudaFuncSetAttribute(k_tgemm,     cudaFuncAttributeMaxDynamicSharedMemorySize, SM_TOT);

    const long ND = (long)NN * DD;
    const int BN_BLOCKS = (int)(ND / 512);
    const int CVT_BLOCKS = (int)(ND / 1024);

    // ---- single-launch weight prep + stats zero ----
    k_wprep_all<<<(int)((LL * WL_STRIDE + 255) / 256), 256>>>(gw1, gw2, wqkv, wo, mw1, mw2);

    k_encode<<<NN, 64>>>(x, pe, atom, pe_w, pe_b);   // h fp32 + h split

    for (int l = 0; l < LL; l++) {
        long off = (long)l * WL_STRIDE;
        const unsigned short* W1h = wh + off,           *W1l = wl + off;
        const unsigned short* W2h = wh + off + 65536,   *W2l = wl + off + 65536;
        const unsigned short* Wqh = wh + off + 131072,  *Wql = wl + off + 131072;
        const unsigned short* Woh = wh + off + 327680,  *Wol = wl + off + 327680;
        const unsigned short* M1h = wh + off + 393216,  *M1l = wl + off + 393216;
        const unsigned short* M2h = wh + off + 524288,  *M2l = wl + off + 524288;

        // --- GINEConv ---
        cudaMemcpyAsync(z, h, ND * sizeof(float), cudaMemcpyDeviceToDevice);
        k_scatter<<<EE / 4, 256>>>(ei, eattr, bond);
        k_acvt<<<CVT_BLOCKS, 256>>>(z, xh, xl);                    // z split
        tgemm(xh, xl, W1h, W1l, gb1 + l * DD, nullptr, t1, nullptr, nullptr, DD, DD, 0, 1, 0);
        // t2 = relu(bn(t1)) -> split only
        k_bn<<<BN_BLOCKS, 256>>>(t1, gg1 + l * DD, gbe1 + l * DD, nullptr, xh, xl, nullptr, 1, 0);
        // t1 = relu(t2@w2+b2) + h ; stats par1
        tgemm(xh, xl, W2h, W2l, gb2 + l * DD, h, t1, nullptr, nullptr, DD, DD, 1, 1, 1);
        // hl = bn(t1) fp32
        k_bn<<<BN_BLOCKS, 256>>>(t1, n1g + l * DD, n1b + l * DD, hl, nullptr, nullptr, nullptr, 0, 1);

        // --- attention branch (A = h split, produced at end of prev layer / encode) ---
        tgemm(hsh, hsl, Wqh, Wql, bqkv + l * 3 * DD, nullptr, qkv, nullptr, nullptr, 3 * DD, DD, 0, 0, 0);
        k_attention<<<dim3(HH, GG), NPG, ATTN_SMEM>>>();           // -> (xh, xl) split
        // t1 = attn@wo+bo + h ; stats par0
        tgemm(xh, xl, Woh, Wol, bo + l * DD, h, t1, nullptr, nullptr, DD, DD, 0, 1, 0);
        // comb = hl + bn(t1) -> split only
        k_bn<<<BN_BLOCKS, 256>>>(t1, n2g + l * DD, n2b + l * DD, nullptr, xh, xl, hl, 0, 0);

        // --- MLP: ff = relu(comb@mw1+mb1) -> split direct from epilogue ---
        tgemm(xh, xl, M1h, M1l, mb1 + l * FF, nullptr, nullptr, fsh, fsl, FF, DD, 1, 0, 0);
        // t1 = ff@mw2+mb2 ; stats par1
        tgemm(fsh, fsl, M2h, M2l, mb2 + l * DD, nullptr, t1, nullptr, nullptr, DD, FF, 0, 1, 1);
        // h = bn(t1) fp32 + split (for next layer qkv)
        k_bn<<<BN_BLOCKS, 256>>>(t1, n3g + l * DD, n3b + l * DD, h, hsh, hsl, nullptr, 0, 1);
    }

    k_pool<<<GG, DD>>>((float*)d_out);
}

// round 16
// speedup vs baseline: 1.0007x; 1.0007x over previous
#include <cuda_runtime.h>
#include <cuda_bf16.h>
#include <math.h>
#include <stdint.h>

// ---------------- problem constants ----------------
constexpr int NN  = 65536;      // nodes
constexpr int DD  = 256;        // hidden
constexpr int EE  = 524288;     // edges
constexpr int LL  = 4;          // layers
constexpr int GG  = 512;        // graphs
constexpr int NPG = 128;        // nodes per graph
constexpr int HH  = 8;          // heads
constexpr int DHH = 32;         // head dim
constexpr int WW  = 20;         // walk length (pe dim)
constexpr int AV  = 128;        // atom vocab
constexpr int BV  = 8;          // bond vocab
constexpr int FF  = 512;        // mlp hidden

// ---------------- scratch (device globals; no alloc allowed) ----------------
__device__ float g_h   [NN * DD];
__device__ float g_z   [NN * DD];
__device__ float g_t1  [NN * DD];
__device__ float g_hl  [NN * DD];
__device__ float g_qkv [NN * 3 * DD];
__device__ float g_sum [2][DD];      // double-buffered BN stats
__device__ float g_ss  [2][DD];

// bf16 hi/lo activation buffers
__device__ unsigned short g_xh [NN * DD];   // z / t2 / attn / comb (sequential reuse)
__device__ unsigned short g_xl [NN * DD];
__device__ unsigned short g_hsh[NN * DD];   // h split (for qkv GEMM)
__device__ unsigned short g_hsl[NN * DD];
__device__ unsigned short g_fsh[NN * FF];   // ff split
__device__ unsigned short g_fsl[NN * FF];

// transposed bf16 hi/lo weights: per layer 655360 elems
// offsets: w1=0, w2=65536, qkv=131072, wo=327680, mlp1=393216, mlp2=524288
constexpr long WL_STRIDE = 655360;
__device__ unsigned short g_wh[LL * WL_STRIDE];
__device__ unsigned short g_wl[LL * WL_STRIDE];

// =====================================================================
// helpers
// =====================================================================
__device__ __forceinline__ uint32_t smem_u32(const void* p) {
    uint32_t a;
    asm("{ .reg .u64 t; cvta.to.shared.u64 t, %1; cvt.u32.u64 %0, t; }" : "=r"(a) : "l"(p));
    return a;
}

#define CPA16(dst, src) \
    asm volatile("cp.async.cg.shared.global [%0], [%1], 16;" \
        :: "r"(dst), "l"(src) : "memory")
#define CPA_COMMIT() asm volatile("cp.async.commit_group;" ::: "memory")
#define CPA_WAIT_ALL() asm volatile("cp.async.wait_group 0;" ::: "memory")

__device__ __forceinline__ void ldsm_x4(uint32_t* r, uint32_t addr) {
    asm volatile("ldmatrix.sync.aligned.m8n8.x4.shared.b16 {%0,%1,%2,%3}, [%4];"
        : "=r"(r[0]), "=r"(r[1]), "=r"(r[2]), "=r"(r[3]) : "r"(addr));
}
__device__ __forceinline__ void ldsm_x2(uint32_t* r, uint32_t addr) {
    asm volatile("ldmatrix.sync.aligned.m8n8.x2.shared.b16 {%0,%1}, [%2];"
        : "=r"(r[0]), "=r"(r[1]) : "r"(addr));
}
__device__ __forceinline__ void mma16816(float* c, const uint32_t* a, const uint32_t* b) {
    asm volatile(
        "mma.sync.aligned.m16n8k16.row.col.f32.bf16.bf16.f32 "
        "{%0,%1,%2,%3}, {%4,%5,%6,%7}, {%8,%9}, {%0,%1,%2,%3};"
        : "+f"(c[0]), "+f"(c[1]), "+f"(c[2]), "+f"(c[3])
        : "r"(a[0]), "r"(a[1]), "r"(a[2]), "r"(a[3]), "r"(b[0]), "r"(b[1]));
}

// split fp32 -> (hi, lo) bf16 pair packed helpers
__device__ __forceinline__ void split2(float a, float b, uint32_t& hi, uint32_t& lo) {
    __nv_bfloat16 h0 = __float2bfloat16_rn(a);
    __nv_bfloat16 h1 = __float2bfloat16_rn(b);
    float r0 = a - __bfloat162float(h0);
    float r1 = b - __bfloat162float(h1);
    __nv_bfloat16 l0 = __float2bfloat16_rn(r0);
    __nv_bfloat16 l1 = __float2bfloat16_rn(r1);
    hi = ((uint32_t)__bfloat16_as_ushort(h1) << 16) | __bfloat16_as_ushort(h0);
    lo = ((uint32_t)__bfloat16_as_ushort(l1) << 16) | __bfloat16_as_ushort(l0);
}

// =====================================================================
// weight prep (single launch): W[K,N] fp32 -> Wt[N,K] bf16 hi/lo
// also zeroes both BN stat buffers (block 0).
// =====================================================================
__global__ void k_wprep_all(const float* __restrict__ gw1, const float* __restrict__ gw2,
                            const float* __restrict__ wqkv, const float* __restrict__ wo,
                            const float* __restrict__ mw1, const float* __restrict__ mw2) {
    if (blockIdx.x == 0) {
        for (int i = threadIdx.x; i < 2 * DD; i += 256) {
            g_sum[i / DD][i % DD] = 0.f;
            g_ss [i / DD][i % DD] = 0.f;
        }
    }
    long idx = (long)blockIdx.x * 256 + threadIdx.x;
    if (idx >= (long)LL * WL_STRIDE) return;
    int l = (int)(idx / WL_STRIDE);
    int r = (int)(idx % WL_STRIDE);
    const float* W; int K, N; int seg; long off;
    if      (r < 65536)  { W = gw1  + (long)l * 65536;  K = 256; N = 256; seg = r;          off = 0; }
    else if (r < 131072) { W = gw2  + (long)l * 65536;  K = 256; N = 256; seg = r - 65536;  off = 65536; }
    else if (r < 327680) { W = wqkv + (long)l * 196608; K = 256; N = 768; seg = r - 131072; off = 131072; }
    else if (r < 393216) { W = wo   + (long)l * 65536;  K = 256; N = 256; seg = r - 327680; off = 327680; }
    else if (r < 524288) { W = mw1  + (long)l * 131072; K = 256; N = 512; seg = r - 393216; off = 393216; }
    else                 { W = mw2  + (long)l * 131072; K = 512; N = 256; seg = r - 524288; off = 524288; }
    int k = seg / N, n = seg % N;
    float v = W[seg];
    __nv_bfloat16 h = __float2bfloat16_rn(v);
    float lo = v - __bfloat162float(h);
    __nv_bfloat16 lw = __float2bfloat16_rn(lo);
    g_wh[(long)l * WL_STRIDE + off + (long)n * K + k] = __bfloat16_as_ushort(h);
    g_wl[(long)l * WL_STRIDE + off + (long)n * K + k] = __bfloat16_as_ushort(lw);
}

// =====================================================================
// activation convert: X fp32 [n] -> Xh/Xl bf16
// =====================================================================
__global__ void k_acvt(const float* __restrict__ X,
                       unsigned short* __restrict__ Xh, unsigned short* __restrict__ Xl) {
    long i4 = ((long)blockIdx.x * 256 + threadIdx.x) * 4;
    float4 v = *(const float4*)(X + i4);
    uint32_t h0, l0, h1, l1;
    split2(v.x, v.y, h0, l0);
    split2(v.z, v.w, h1, l1);
    *(uint2*)(Xh + i4) = make_uint2(h0, h1);
    *(uint2*)(Xl + i4) = make_uint2(l0, l1);
}

// =====================================================================
// mma.sync GEMM: C[M,Nn] = A[M,K] @ B[K,Nn] + bias (+relu) (+res)
//                (+BN stats) ; output fp32 OR bf16 hi/lo split
// A and B both pre-split bf16 hi/lo. 3 products: hh + hl + lh.
// CTA tile 128x128, warp tile 32x64, K-chunk 32, 256 threads, occ 2.
// 2-stage cp.async double buffer; one syncthreads per chunk.
// smem rows 64B data + 16B pad = 80B -> conflict-free ldmatrix.
// =====================================================================
constexpr int ROWB  = 80;
constexpr int MAT   = 128 * ROWB;       // 10240
constexpr int SA_H  = 0;
constexpr int SA_L  = MAT;
constexpr int SB_H  = 2 * MAT;
constexpr int SB_L  = 3 * MAT;
constexpr int STAGE = 4 * MAT;          // 40960
constexpr int SM_TOT = 2 * STAGE;       // 81920

__global__ void __launch_bounds__(256, 2) k_tgemm(
    const unsigned short* __restrict__ Ah, const unsigned short* __restrict__ Al,
    const unsigned short* __restrict__ Bh, const unsigned short* __restrict__ Bl,
    const float* __restrict__ bias, const float* __restrict__ res,
    float* __restrict__ Cf,
    unsigned short* __restrict__ Ch, unsigned short* __restrict__ Cl,
    int Nn, int K, int relu, int do_stats, int par)
{
    extern __shared__ char smbuf[];
    uint32_t sb = smem_u32(smbuf);
    int tid = threadIdx.x, wid = tid >> 5, lane = tid & 31;
    int m0 = blockIdx.y * 128;
    int n0 = blockIdx.x * 128;
    const int wm = (wid & 3) * 32;
    const int wn = (wid >> 2) * 64;

    float acc[2][8][4];
#pragma unroll
    for (int i = 0; i < 2; i++)
#pragma unroll
        for (int j = 0; j < 8; j++)
#pragma unroll
            for (int q = 0; q < 4; q++) acc[i][j][q] = 0.f;

    // loader mapping: 2 threads per row, 16 elems (32B) each
    const int lr = tid >> 1;
    const int le = (tid & 1) * 16;       // elem offset in chunk
    const unsigned short* ah = Ah + (long)(m0 + lr) * K + le;
    const unsigned short* al = Al + (long)(m0 + lr) * K + le;
    const unsigned short* bh = Bh + (long)(n0 + lr) * K + le;
    const unsigned short* bl = Bl + (long)(n0 + lr) * K + le;
    const uint32_t sd = sb + (uint32_t)(lr * ROWB + (tid & 1) * 32);

    const int nch = K >> 5;

    // ldmatrix per-lane patterns
    const int a_row = lane & 15;
    const int a_cb  = (lane >> 4) * 16;
    const int b_row = lane & 7;
    const int b_cb  = ((lane >> 3) & 1) * 16;

    // prologue: chunk 0 -> stage 0
    {
        CPA16(sd + SA_H, ah); CPA16(sd + SA_H + 16, ah + 8);
        CPA16(sd + SA_L, al); CPA16(sd + SA_L + 16, al + 8);
        CPA16(sd + SB_H, bh); CPA16(sd + SB_H + 16, bh + 8);
        CPA16(sd + SB_L, bl); CPA16(sd + SB_L + 16, bl + 8);
        CPA_COMMIT();
    }

    for (int c = 0; c < nch; c++) {
        const uint32_t sbp = sb + (uint32_t)((c & 1) * STAGE);
        CPA_WAIT_ALL();      // chunk c landed
        __syncthreads();     // visible to all; stage (c+1)&1 free (consumed at c-1)
        if (c + 1 < nch) {
            const int kc = (c + 1) * 32;
            const uint32_t nd = sd + (uint32_t)(((c + 1) & 1) * STAGE);
            CPA16(nd + SA_H, ah + kc); CPA16(nd + SA_H + 16, ah + kc + 8);
            CPA16(nd + SA_L, al + kc); CPA16(nd + SA_L + 16, al + kc + 8);
            CPA16(nd + SB_H, bh + kc); CPA16(nd + SB_H + 16, bh + kc + 8);
            CPA16(nd + SB_L, bl + kc); CPA16(nd + SB_L + 16, bl + kc + 8);
            CPA_COMMIT();
        }
        // ---- MMA chunk c: 2 k-steps x (2 mf x 8 nf) x 3 products ----
#pragma unroll
        for (int ks = 0; ks < 2; ks++) {
            uint32_t ahf[2][4], alf[2][4];
#pragma unroll
            for (int mf = 0; mf < 2; mf++) {
                uint32_t aaddr = sbp + SA_H +
                    (uint32_t)((wm + mf * 16 + a_row) * ROWB + ks * 32 + a_cb);
                ldsm_x4(ahf[mf], aaddr);
                ldsm_x4(alf[mf], aaddr + MAT);
            }
#pragma unroll
            for (int nf = 0; nf < 8; nf++) {
                uint32_t baddr = sbp + SB_H +
                    (uint32_t)((wn + nf * 8 + b_row) * ROWB + ks * 32 + b_cb);
                uint32_t bh2[2], bl2[2];
                ldsm_x2(bh2, baddr);
                ldsm_x2(bl2, baddr + MAT);
#pragma unroll
                for (int mf = 0; mf < 2; mf++) {
                    mma16816(acc[mf][nf], ahf[mf], bh2);
                    mma16816(acc[mf][nf], ahf[mf], bl2);
                    mma16816(acc[mf][nf], alf[mf], bh2);
                }
            }
        }
    }

    // ---- epilogue ----
    float s[16], q2[16];
#pragma unroll
    for (int i = 0; i < 16; i++) { s[i] = 0.f; q2[i] = 0.f; }

#pragma unroll
    for (int mf = 0; mf < 2; mf++) {
        int row0 = m0 + wm + mf * 16 + (lane >> 2);
#pragma unroll
        for (int nf = 0; nf < 8; nf++) {
            int col = n0 + wn + nf * 8 + (lane & 3) * 2;
            float2 bv = *(const float2*)(bias + col);
            float c0 = acc[mf][nf][0] + bv.x;
            float c1 = acc[mf][nf][1] + bv.y;
            float c2 = acc[mf][nf][2] + bv.x;
            float c3 = acc[mf][nf][3] + bv.y;
            if (relu) {
                c0 = fmaxf(c0, 0.f); c1 = fmaxf(c1, 0.f);
                c2 = fmaxf(c2, 0.f); c3 = fmaxf(c3, 0.f);
            }
            if (res) {
                float2 r0 = *(const float2*)(res + (long)row0 * Nn + col);
                float2 r1 = *(const float2*)(res + (long)(row0 + 8) * Nn + col);
                c0 += r0.x; c1 += r0.y; c2 += r1.x; c3 += r1.y;
            }
            if (Cf) {
                *(float2*)(Cf + (long)row0 * Nn + col) = make_float2(c0, c1);
                *(float2*)(Cf + (long)(row0 + 8) * Nn + col) = make_float2(c2, c3);
            }
            if (Ch) {
                uint32_t h0, l0, h1, l1;
                split2(c0, c1, h0, l0);
                split2(c2, c3, h1, l1);
                *(uint32_t*)(Ch + (long)row0 * Nn + col) = h0;
                *(uint32_t*)(Cl + (long)row0 * Nn + col) = l0;
                *(uint32_t*)(Ch + (long)(row0 + 8) * Nn + col) = h1;
                *(uint32_t*)(Cl + (long)(row0 + 8) * Nn + col) = l1;
            }
            if (do_stats) {
                s[nf * 2 + 0]  += c0 + c2;
                s[nf * 2 + 1]  += c1 + c3;
                q2[nf * 2 + 0] += c0 * c0 + c2 * c2;
                q2[nf * 2 + 1] += c1 * c1 + c3 * c3;
            }
        }
    }
    if (do_stats) {
#pragma unroll
        for (int i = 0; i < 16; i++) {
#pragma unroll
            for (int m = 4; m <= 16; m <<= 1) {
                s[i]  += __shfl_xor_sync(0xffffffffu, s[i],  m);
                q2[i] += __shfl_xor_sync(0xffffffffu, q2[i], m);
            }
        }
        if ((lane >> 2) == 0) {
#pragma unroll
            for (int nf = 0; nf < 8; nf++) {
                int col = n0 + wn + nf * 8 + lane * 2;
                atomicAdd(&g_sum[par][col],     s[nf * 2 + 0]);
                atomicAdd(&g_sum[par][col + 1], s[nf * 2 + 1]);
                atomicAdd(&g_ss[par][col],      q2[nf * 2 + 0]);
                atomicAdd(&g_ss[par][col + 1],  q2[nf * 2 + 1]);
            }
        }
    }
}

// =====================================================================
// non-GEMM kernels
// =====================================================================
__global__ void k_encode(const int* __restrict__ x, const float* __restrict__ pe,
                         const float* __restrict__ atom, const float* __restrict__ pe_w,
                         const float* __restrict__ pe_b) {
    int n = blockIdx.x;
    int d = threadIdx.x * 4;
    __shared__ int   xs[9];
    __shared__ float ps[WW];
    if (threadIdx.x < 9) xs[threadIdx.x] = x[n * 9 + threadIdx.x];
    if (threadIdx.x >= 32 && threadIdx.x < 32 + WW) ps[threadIdx.x - 32] = pe[n * WW + (threadIdx.x - 32)];
    __syncthreads();
    float4 acc = *(const float4*)(pe_b + d);
#pragma unroll
    for (int c = 0; c < 9; c++) {
        float4 v = *(const float4*)(atom + ((long)(c * AV + xs[c]) * DD + d));
        acc.x += v.x; acc.y += v.y; acc.z += v.z; acc.w += v.w;
    }
#pragma unroll
    for (int w = 0; w < WW; w++) {
        float p = ps[w];
        float4 v = *(const float4*)(pe_w + (long)w * DD + d);
        acc.x = fmaf(p, v.x, acc.x); acc.y = fmaf(p, v.y, acc.y);
        acc.z = fmaf(p, v.z, acc.z); acc.w = fmaf(p, v.w, acc.w);
    }
    long o = (long)n * DD + d;
    *(float4*)(g_h + o) = acc;
    uint32_t h0, l0, h1, l1;
    split2(acc.x, acc.y, h0, l0);
    split2(acc.z, acc.w, h1, l1);
    *(uint2*)(g_hsh + o) = make_uint2(h0, h1);
    *(uint2*)(g_hsl + o) = make_uint2(l0, l1);
}

__global__ void k_scatter(const int* __restrict__ ei, const int* __restrict__ eattr,
                          const float* __restrict__ bond) {
    int le = threadIdx.x >> 6;
    int d  = (threadIdx.x & 63) * 4;
    long e = (long)blockIdx.x * 4 + le;
    int src = ei[e];
    int dst = ei[(long)EE + e];
    int a0 = eattr[e * 3 + 0], a1 = eattr[e * 3 + 1], a2 = eattr[e * 3 + 2];
    float4 hv = *(const float4*)(g_h + (long)src * DD + d);
    float4 b0 = *(const float4*)(bond + (long)(0 * BV + a0) * DD + d);
    float4 b1 = *(const float4*)(bond + (long)(1 * BV + a1) * DD + d);
    float4 b2 = *(const float4*)(bond + (long)(2 * BV + a2) * DD + d);
    float m0 = fmaxf(hv.x + b0.x + b1.x + b2.x, 0.f);
    float m1 = fmaxf(hv.y + b0.y + b1.y + b2.y, 0.f);
    float m2 = fmaxf(hv.z + b0.z + b1.z + b2.z, 0.f);
    float m3 = fmaxf(hv.w + b0.w + b1.w + b2.w, 0.f);
    float* zp = g_z + (long)dst * DD + d;
    atomicAdd(zp + 0, m0); atomicAdd(zp + 1, m1);
    atomicAdd(zp + 2, m2); atomicAdd(zp + 3, m3);
}

// BatchNorm apply. Outputs: optional fp32 Ofp, optional split (Oh,Ol).
// Optional post-bn residual add (radd). Zeroes stats[par^1].
__global__ void k_bn(const float* __restrict__ A,
                     const float* __restrict__ gma, const float* __restrict__ bta,
                     float* __restrict__ Ofp,
                     unsigned short* __restrict__ Oh, unsigned short* __restrict__ Ol,
                     const float* __restrict__ radd, int relu, int par) {
    long i = ((long)blockIdx.x * 256 + threadIdx.x) * 2;
    int d = (int)(i & (DD - 1));
    float2 mu2 = *(const float2*)(&g_sum[par][d]);
    float2 ss2 = *(const float2*)(&g_ss[par][d]);
    float2 gm  = *(const float2*)(gma + d);
    float2 bt  = *(const float2*)(bta + d);
    float2 va  = *(const float2*)(A + i);
    float mu0 = mu2.x * (1.f / NN), mu1 = mu2.y * (1.f / NN);
    float v0 = (va.x - mu0) * rsqrtf(ss2.x * (1.f / NN) - mu0 * mu0 + 1e-5f) * gm.x + bt.x;
    float v1 = (va.y - mu1) * rsqrtf(ss2.y * (1.f / NN) - mu1 * mu1 + 1e-5f) * gm.y + bt.y;
    if (relu) { v0 = fmaxf(v0, 0.f); v1 = fmaxf(v1, 0.f); }
    if (radd) {
        float2 r = *(const float2*)(radd + i);
        v0 += r.x; v1 += r.y;
    }
    if (Ofp) *(float2*)(Ofp + i) = make_float2(v0, v1);
    if (Oh) {
        uint32_t h0, l0;
        split2(v0, v1, h0, l0);
        *(uint32_t*)(Oh + i) = h0;
        *(uint32_t*)(Ol + i) = l0;
    }
    if (blockIdx.x == 0 && threadIdx.x < DD / 2) {
        *(float2*)(&g_sum[par ^ 1][threadIdx.x * 2]) = make_float2(0.f, 0.f);
        *(float2*)(&g_ss [par ^ 1][threadIdx.x * 2]) = make_float2(0.f, 0.f);
    }
}

constexpr int ATTN_SMEM = (2 * NPG * 33 + NPG * 129) * 4;
__global__ void k_attention() {
    extern __shared__ float sm[];
    float* Ks = sm;
    float* Vs = Ks + NPG * 33;
    float* Ss = Vs + NPG * 33;
    int head = blockIdx.x, g = blockIdx.y;
    int i = threadIdx.x;
    const float* base = g_qkv + (long)(g * NPG + i) * (3 * DD);

    float q[DHH];
#pragma unroll
    for (int k = 0; k < DHH; k++) {
        q[k] = base[head * DHH + k];
        Ks[i * 33 + k] = base[DD + head * DHH + k];
        Vs[i * 33 + k] = base[2 * DD + head * DHH + k];
    }
    __syncthreads();

    const float scale = 0.17677669529663688f;
    float mx = -1e30f;
#pragma unroll 4
    for (int j = 0; j < NPG; j++) {
        float sv = 0.f;
#pragma unroll
        for (int k = 0; k < DHH; k++) sv = fmaf(q[k], Ks[j * 33 + k], sv);
        sv *= scale;
        Ss[i * 129 + j] = sv;
        mx = fmaxf(mx, sv);
    }
    float denom = 0.f;
#pragma unroll 4
    for (int j = 0; j < NPG; j++) {
        float p = __expf(Ss[i * 129 + j] - mx);
        Ss[i * 129 + j] = p;
        denom += p;
    }
    float inv = 1.f / denom;
    float o[DHH];
#pragma unroll
    for (int k = 0; k < DHH; k++) o[k] = 0.f;
#pragma unroll 4
    for (int j = 0; j < NPG; j++) {
        float p = Ss[i * 129 + j];
#pragma unroll
        for (int k = 0; k < DHH; k++) o[k] = fmaf(p, Vs[j * 33 + k], o[k]);
    }
    // write split bf16 hi/lo (attn only feeds the wo GEMM)
    long ob = (long)(g * NPG + i) * DD + head * DHH;
#pragma unroll
    for (int k = 0; k < DHH; k += 2) {
        uint32_t h0, l0;
        split2(o[k] * inv, o[k + 1] * inv, h0, l0);
        *(uint32_t*)(g_xh + ob + k) = h0;
        *(uint32_t*)(g_xl + ob + k) = l0;
    }
}

__global__ void k_pool(float* __restrict__ out) {
    int g = blockIdx.x, d = threadIdx.x;
    float s = 0.f;
    for (int i = 0; i < NPG; i++) s += g_h[(long)(g * NPG + i) * DD + d];
    out[g * DD + d] = s;
}

// =====================================================================
// host orchestration
// =====================================================================
static void tgemm(const unsigned short* Ah, const unsigned short* Al,
                  const unsigned short* Bh, const unsigned short* Bl,
                  const float* bias, const float* res,
                  float* Cf, unsigned short* Ch, unsigned short* Cl,
                  int Nn, int K, int relu, int do_stats, int par) {
    dim3 grid(Nn / 128, NN / 128);
    k_tgemm<<<grid, 256, SM_TOT>>>(Ah, Al, Bh, Bl, bias, res, Cf, Ch, Cl,
                                   Nn, K, relu, do_stats, par);
}

extern "C" void kernel_launch(void* const* d_in, const int* in_sizes, int n_in,
                              void* d_out, int out_size) {
    const int*   x     = (const int*)d_in[0];
    const int*   ei    = (const int*)d_in[1];
    const int*   eattr = (const int*)d_in[2];
    const float* pe    = (const float*)d_in[4];
    const float* atom  = (const float*)d_in[5];
    const float* bond  = (const float*)d_in[6];
    const float* pe_w  = (const float*)d_in[7];
    const float* pe_b  = (const float*)d_in[8];
    const float* gw1   = (const float*)d_in[9];
    const float* gb1   = (const float*)d_in[10];
    const float* gg1   = (const float*)d_in[11];
    const float* gbe1  = (const float*)d_in[12];
    const float* gw2   = (const float*)d_in[13];
    const float* gb2   = (const float*)d_in[14];
    const float* wqkv  = (const float*)d_in[15];
    const float* bqkv  = (const float*)d_in[16];
    const float* wo    = (const float*)d_in[17];
    const float* bo    = (const float*)d_in[18];
    const float* n1g   = (const float*)d_in[19];
    const float* n1b   = (const float*)d_in[20];
    const float* n2g   = (const float*)d_in[21];
    const float* n2b   = (const float*)d_in[22];
    const float* n3g   = (const float*)d_in[23];
    const float* n3b   = (const float*)d_in[24];
    const float* mw1   = (const float*)d_in[25];
    const float* mb1   = (const float*)d_in[26];
    const float* mw2   = (const float*)d_in[27];
    const float* mb2   = (const float*)d_in[28];

    float *h, *z, *t1, *hl, *qkv;
    unsigned short *wh, *wl, *xh, *xl, *hsh, *hsl, *fsh, *fsl;
    cudaGetSymbolAddress((void**)&h,    g_h);
    cudaGetSymbolAddress((void**)&z,    g_z);
    cudaGetSymbolAddress((void**)&t1,   g_t1);
    cudaGetSymbolAddress((void**)&hl,   g_hl);
    cudaGetSymbolAddress((void**)&qkv,  g_qkv);
    cudaGetSymbolAddress((void**)&wh,   g_wh);
    cudaGetSymbolAddress((void**)&wl,   g_wl);
    cudaGetSymbolAddress((void**)&xh,   g_xh);
    cudaGetSymbolAddress((void**)&xl,   g_xl);
    cudaGetSymbolAddress((void**)&hsh,  g_hsh);
    cudaGetSymbolAddress((void**)&hsl,  g_hsl);
    cudaGetSymbolAddress((void**)&fsh,  g_fsh);
    cudaGetSymbolAddress((void**)&fsl,  g_fsl);

    cudaFuncSetAttribute(k_attention, cudaFuncAttributeMaxDynamicSharedMemorySize, ATTN_SMEM);
    cudaFuncSetAttribute(k_tgemm,     cudaFuncAttributeMaxDynamicSharedMemorySize, SM_TOT);

    const long ND = (long)NN * DD;
    const int BN_BLOCKS = (int)(ND / 512);
    const int CVT_BLOCKS = (int)(ND / 1024);

    // ---- single-launch weight prep + stats zero ----
    k_wprep_all<<<(int)((LL * WL_STRIDE + 255) / 256), 256>>>(gw1, gw2, wqkv, wo, mw1, mw2);

    k_encode<<<NN, 64>>>(x, pe, atom, pe_w, pe_b);   // h fp32 + h split

    for (int l = 0; l < LL; l++) {
        long off = (long)l * WL_STRIDE;
        const unsigned short* W1h = wh + off,           *W1l = wl + off;
        const unsigned short* W2h = wh + off + 65536,   *W2l = wl + off + 65536;
        const unsigned short* Wqh = wh + off + 131072,  *Wql = wl + off + 131072;
        const unsigned short* Woh = wh + off + 327680,  *Wol = wl + off + 327680;
        const unsigned short* M1h = wh + off + 393216,  *M1l = wl + off + 393216;
        const unsigned short* M2h = wh + off + 524288,  *M2l = wl + off + 524288;

        // --- GINEConv ---
        cudaMemcpyAsync(z, h, ND * sizeof(float), cudaMemcpyDeviceToDevice);
        k_scatter<<<EE / 4, 256>>>(ei, eattr, bond);
        k_acvt<<<CVT_BLOCKS, 256>>>(z, xh, xl);                    // z split
        tgemm(xh, xl, W1h, W1l, gb1 + l * DD, nullptr, t1, nullptr, nullptr, DD, DD, 0, 1, 0);
        // t2 = relu(bn(t1)) -> split only
        k_bn<<<BN_BLOCKS, 256>>>(t1, gg1 + l * DD, gbe1 + l * DD, nullptr, xh, xl, nullptr, 1, 0);
        // t1 = relu(t2@w2+b2) + h ; stats par1
        tgemm(xh, xl, W2h, W2l, gb2 + l * DD, h, t1, nullptr, nullptr, DD, DD, 1, 1, 1);
        // hl = bn(t1) fp32
        k_bn<<<BN_BLOCKS, 256>>>(t1, n1g + l * DD, n1b + l * DD, hl, nullptr, nullptr, nullptr, 0, 1);

        // --- attention branch (A = h split, produced at end of prev layer / encode) ---
        tgemm(hsh, hsl, Wqh, Wql, bqkv + l * 3 * DD, nullptr, qkv, nullptr, nullptr, 3 * DD, DD, 0, 0, 0);
        k_attention<<<dim3(HH, GG), NPG, ATTN_SMEM>>>();           // -> (xh, xl) split
        // t1 = attn@wo+bo + h ; stats par0
        tgemm(xh, xl, Woh, Wol, bo + l * DD, h, t1, nullptr, nullptr, DD, DD, 0, 1, 0);
        // comb = hl + bn(t1) -> split only
        k_bn<<<BN_BLOCKS, 256>>>(t1, n2g + l * DD, n2b + l * DD, nullptr, xh, xl, hl, 0, 0);

        // --- MLP: ff = relu(comb@mw1+mb1) -> split direct from epilogue ---
        tgemm(xh, xl, M1h, M1l, mb1 + l * FF, nullptr, nullptr, fsh, fsl, FF, DD, 1, 0, 0);
        // t1 = ff@mw2+mb2 ; stats par1
        tgemm(fsh, fsl, M2h, M2l, mb2 + l * DD, nullptr, t1, nullptr, nullptr, DD, FF, 0, 1, 1);
        // h = bn(t1) fp32 + split (for next layer qkv)
        k_bn<<<BN_BLOCKS, 256>>>(t1, n3g + l * DD, n3b + l * DD, h, hsh, hsl, nullptr, 0, 1);
    }

    k_pool<<<GG, DD>>>((float*)d_out);
}

// round 17
// speedup vs baseline: 1.0049x; 1.0042x over previous
#include <cuda_runtime.h>
#include <cuda_bf16.h>
#include <math.h>
#include <stdint.h>

// ---------------- problem constants ----------------
constexpr int NN  = 65536;      // nodes
constexpr int DD  = 256;        // hidden
constexpr int EE  = 524288;     // edges
constexpr int LL  = 4;          // layers
constexpr int GG  = 512;        // graphs
constexpr int NPG = 128;        // nodes per graph
constexpr int HH  = 8;          // heads
constexpr int DHH = 32;         // head dim
constexpr int WW  = 20;         // walk length (pe dim)
constexpr int AV  = 128;        // atom vocab
constexpr int BV  = 8;          // bond vocab
constexpr int FF  = 512;        // mlp hidden

// ---------------- scratch (device globals; no alloc allowed) ----------------
__device__ float g_h   [NN * DD];
__device__ float g_z   [NN * DD];
__device__ float g_t1  [NN * DD];
__device__ float g_hl  [NN * DD];
__device__ float g_qkv [NN * 3 * DD];
__device__ float g_sum [2][DD];      // double-buffered BN stats
__device__ float g_ss  [2][DD];

// bf16 hi/lo activation buffers
__device__ unsigned short g_xh [NN * DD];   // z / t2 / attn / comb (sequential reuse)
__device__ unsigned short g_xl [NN * DD];
__device__ unsigned short g_hsh[NN * DD];   // h split (for qkv GEMM)
__device__ unsigned short g_hsl[NN * DD];
__device__ unsigned short g_fsh[NN * FF];   // ff split
__device__ unsigned short g_fsl[NN * FF];

// transposed bf16 hi/lo weights: per layer 655360 elems
// offsets: w1=0, w2=65536, qkv=131072, wo=327680, mlp1=393216, mlp2=524288
constexpr long WL_STRIDE = 655360;
__device__ unsigned short g_wh[LL * WL_STRIDE];
__device__ unsigned short g_wl[LL * WL_STRIDE];

// =====================================================================
// helpers
// =====================================================================
__device__ __forceinline__ uint32_t smem_u32(const void* p) {
    uint32_t a;
    asm("{ .reg .u64 t; cvta.to.shared.u64 t, %1; cvt.u32.u64 %0, t; }" : "=r"(a) : "l"(p));
    return a;
}

#define CPA16(dst, src) \
    asm volatile("cp.async.cg.shared.global [%0], [%1], 16;" \
        :: "r"(dst), "l"(src) : "memory")
#define CPA_COMMIT() asm volatile("cp.async.commit_group;" ::: "memory")
#define CPA_WAIT_ALL() asm volatile("cp.async.wait_group 0;" ::: "memory")

__device__ __forceinline__ void ldsm_x4(uint32_t* r, uint32_t addr) {
    asm volatile("ldmatrix.sync.aligned.m8n8.x4.shared.b16 {%0,%1,%2,%3}, [%4];"
        : "=r"(r[0]), "=r"(r[1]), "=r"(r[2]), "=r"(r[3]) : "r"(addr));
}
__device__ __forceinline__ void ldsm_x2(uint32_t* r, uint32_t addr) {
    asm volatile("ldmatrix.sync.aligned.m8n8.x2.shared.b16 {%0,%1}, [%2];"
        : "=r"(r[0]), "=r"(r[1]) : "r"(addr));
}
__device__ __forceinline__ void mma16816(float* c, const uint32_t* a, const uint32_t* b) {
    asm volatile(
        "mma.sync.aligned.m16n8k16.row.col.f32.bf16.bf16.f32 "
        "{%0,%1,%2,%3}, {%4,%5,%6,%7}, {%8,%9}, {%0,%1,%2,%3};"
        : "+f"(c[0]), "+f"(c[1]), "+f"(c[2]), "+f"(c[3])
        : "r"(a[0]), "r"(a[1]), "r"(a[2]), "r"(a[3]), "r"(b[0]), "r"(b[1]));
}

// split fp32 -> (hi, lo) bf16 pair packed helpers
__device__ __forceinline__ void split2(float a, float b, uint32_t& hi, uint32_t& lo) {
    __nv_bfloat16 h0 = __float2bfloat16_rn(a);
    __nv_bfloat16 h1 = __float2bfloat16_rn(b);
    float r0 = a - __bfloat162float(h0);
    float r1 = b - __bfloat162float(h1);
    __nv_bfloat16 l0 = __float2bfloat16_rn(r0);
    __nv_bfloat16 l1 = __float2bfloat16_rn(r1);
    hi = ((uint32_t)__bfloat16_as_ushort(h1) << 16) | __bfloat16_as_ushort(h0);
    lo = ((uint32_t)__bfloat16_as_ushort(l1) << 16) | __bfloat16_as_ushort(l0);
}

// =====================================================================
// weight prep (single launch): W[K,N] fp32 -> Wt[N,K] bf16 hi/lo
// also zeroes both BN stat buffers (block 0).
// =====================================================================
__global__ void k_wprep_all(const float* __restrict__ gw1, const float* __restrict__ gw2,
                            const float* __restrict__ wqkv, const float* __restrict__ wo,
                            const float* __restrict__ mw1, const float* __restrict__ mw2) {
    if (blockIdx.x == 0) {
        for (int i = threadIdx.x; i < 2 * DD; i += 256) {
            g_sum[i / DD][i % DD] = 0.f;
            g_ss [i / DD][i % DD] = 0.f;
        }
    }
    long idx = (long)blockIdx.x * 256 + threadIdx.x;
    if (idx >= (long)LL * WL_STRIDE) return;
    int l = (int)(idx / WL_STRIDE);
    int r = (int)(idx % WL_STRIDE);
    const float* W; int K, N; int seg; long off;
    if      (r < 65536)  { W = gw1  + (long)l * 65536;  K = 256; N = 256; seg = r;          off = 0; }
    else if (r < 131072) { W = gw2  + (long)l * 65536;  K = 256; N = 256; seg = r - 65536;  off = 65536; }
    else if (r < 327680) { W = wqkv + (long)l * 196608; K = 256; N = 768; seg = r - 131072; off = 131072; }
    else if (r < 393216) { W = wo   + (long)l * 65536;  K = 256; N = 256; seg = r - 327680; off = 327680; }
    else if (r < 524288) { W = mw1  + (long)l * 131072; K = 256; N = 512; seg = r - 393216; off = 393216; }
    else                 { W = mw2  + (long)l * 131072; K = 512; N = 256; seg = r - 524288; off = 524288; }
    int k = seg / N, n = seg % N;
    float v = W[seg];
    __nv_bfloat16 h = __float2bfloat16_rn(v);
    float lo = v - __bfloat162float(h);
    __nv_bfloat16 lw = __float2bfloat16_rn(lo);
    g_wh[(long)l * WL_STRIDE + off + (long)n * K + k] = __bfloat16_as_ushort(h);
    g_wl[(long)l * WL_STRIDE + off + (long)n * K + k] = __bfloat16_as_ushort(lw);
}

// =====================================================================
// activation convert: X fp32 [n] -> Xh/Xl bf16
// =====================================================================
__global__ void k_acvt(const float* __restrict__ X,
                       unsigned short* __restrict__ Xh, unsigned short* __restrict__ Xl) {
    long i4 = ((long)blockIdx.x * 256 + threadIdx.x) * 4;
    float4 v = *(const float4*)(X + i4);
    uint32_t h0, l0, h1, l1;
    split2(v.x, v.y, h0, l0);
    split2(v.z, v.w, h1, l1);
    *(uint2*)(Xh + i4) = make_uint2(h0, h1);
    *(uint2*)(Xl + i4) = make_uint2(l0, l1);
}

// =====================================================================
// mma.sync GEMM: C[M,Nn] = A[M,K] @ B[K,Nn] + bias (+relu) (+res)
//                (+BN stats) ; output fp32 OR bf16 hi/lo split
// A and B both pre-split bf16 hi/lo. 3 products: hh + hl + lh.
// CTA tile 128x128, warp tile 32x64, K-chunk 32, 256 threads, occ 2.
// 2-stage cp.async double buffer; one syncthreads per chunk.
// smem rows 64B data + 16B pad = 80B -> conflict-free ldmatrix.
// =====================================================================
constexpr int ROWB  = 80;
constexpr int MAT   = 128 * ROWB;       // 10240
constexpr int SA_H  = 0;
constexpr int SA_L  = MAT;
constexpr int SB_H  = 2 * MAT;
constexpr int SB_L  = 3 * MAT;
constexpr int STAGE = 4 * MAT;          // 40960
constexpr int SM_TOT = 2 * STAGE;       // 81920

__global__ void __launch_bounds__(256, 2) k_tgemm(
    const unsigned short* __restrict__ Ah, const unsigned short* __restrict__ Al,
    const unsigned short* __restrict__ Bh, const unsigned short* __restrict__ Bl,
    const float* __restrict__ bias, const float* __restrict__ res,
    float* __restrict__ Cf,
    unsigned short* __restrict__ Ch, unsigned short* __restrict__ Cl,
    int Nn, int K, int relu, int do_stats, int par)
{
    extern __shared__ char smbuf[];
    uint32_t sb = smem_u32(smbuf);
    int tid = threadIdx.x, wid = tid >> 5, lane = tid & 31;
    int m0 = blockIdx.y * 128;
    int n0 = blockIdx.x * 128;
    const int wm = (wid & 3) * 32;
    const int wn = (wid >> 2) * 64;

    float acc[2][8][4];
#pragma unroll
    for (int i = 0; i < 2; i++)
#pragma unroll
        for (int j = 0; j < 8; j++)
#pragma unroll
            for (int q = 0; q < 4; q++) acc[i][j][q] = 0.f;

    // loader mapping: 2 threads per row, 16 elems (32B) each
    const int lr = tid >> 1;
    const int le = (tid & 1) * 16;       // elem offset in chunk
    const unsigned short* ah = Ah + (long)(m0 + lr) * K + le;
    const unsigned short* al = Al + (long)(m0 + lr) * K + le;
    const unsigned short* bh = Bh + (long)(n0 + lr) * K + le;
    const unsigned short* bl = Bl + (long)(n0 + lr) * K + le;
    const uint32_t sd = sb + (uint32_t)(lr * ROWB + (tid & 1) * 32);

    const int nch = K >> 5;

    // ldmatrix per-lane patterns
    const int a_row = lane & 15;
    const int a_cb  = (lane >> 4) * 16;
    const int b_row = lane & 7;
    const int b_cb  = ((lane >> 3) & 1) * 16;

    // prologue: chunk 0 -> stage 0
    {
        CPA16(sd + SA_H, ah); CPA16(sd + SA_H + 16, ah + 8);
        CPA16(sd + SA_L, al); CPA16(sd + SA_L + 16, al + 8);
        CPA16(sd + SB_H, bh); CPA16(sd + SB_H + 16, bh + 8);
        CPA16(sd + SB_L, bl); CPA16(sd + SB_L + 16, bl + 8);
        CPA_COMMIT();
    }

    for (int c = 0; c < nch; c++) {
        const uint32_t sbp = sb + (uint32_t)((c & 1) * STAGE);
        CPA_WAIT_ALL();      // chunk c landed
        __syncthreads();     // visible to all; stage (c+1)&1 free (consumed at c-1)
        if (c + 1 < nch) {
            const int kc = (c + 1) * 32;
            const uint32_t nd = sd + (uint32_t)(((c + 1) & 1) * STAGE);
            CPA16(nd + SA_H, ah + kc); CPA16(nd + SA_H + 16, ah + kc + 8);
            CPA16(nd + SA_L, al + kc); CPA16(nd + SA_L + 16, al + kc + 8);
            CPA16(nd + SB_H, bh + kc); CPA16(nd + SB_H + 16, bh + kc + 8);
            CPA16(nd + SB_L, bl + kc); CPA16(nd + SB_L + 16, bl + kc + 8);
            CPA_COMMIT();
        }
        // ---- MMA chunk c: 2 k-steps x (2 mf x 8 nf) x 3 products ----
#pragma unroll
        for (int ks = 0; ks < 2; ks++) {
            uint32_t ahf[2][4], alf[2][4];
#pragma unroll
            for (int mf = 0; mf < 2; mf++) {
                uint32_t aaddr = sbp + SA_H +
                    (uint32_t)((wm + mf * 16 + a_row) * ROWB + ks * 32 + a_cb);
                ldsm_x4(ahf[mf], aaddr);
                ldsm_x4(alf[mf], aaddr + MAT);
            }
#pragma unroll
            for (int nf = 0; nf < 8; nf++) {
                uint32_t baddr = sbp + SB_H +
                    (uint32_t)((wn + nf * 8 + b_row) * ROWB + ks * 32 + b_cb);
                uint32_t bh2[2], bl2[2];
                ldsm_x2(bh2, baddr);
                ldsm_x2(bl2, baddr + MAT);
#pragma unroll
                for (int mf = 0; mf < 2; mf++) {
                    mma16816(acc[mf][nf], ahf[mf], bh2);
                    mma16816(acc[mf][nf], ahf[mf], bl2);
                    mma16816(acc[mf][nf], alf[mf], bh2);
                }
            }
        }
    }

    // ---- epilogue ----
    float s[16], q2[16];
#pragma unroll
    for (int i = 0; i < 16; i++) { s[i] = 0.f; q2[i] = 0.f; }

#pragma unroll
    for (int mf = 0; mf < 2; mf++) {
        int row0 = m0 + wm + mf * 16 + (lane >> 2);
#pragma unroll
        for (int nf = 0; nf < 8; nf++) {
            int col = n0 + wn + nf * 8 + (lane & 3) * 2;
            float2 bv = *(const float2*)(bias + col);
            float c0 = acc[mf][nf][0] + bv.x;
            float c1 = acc[mf][nf][1] + bv.y;
            float c2 = acc[mf][nf][2] + bv.x;
            float c3 = acc[mf][nf][3] + bv.y;
            if (relu) {
                c0 = fmaxf(c0, 0.f); c1 = fmaxf(c1, 0.f);
                c2 = fmaxf(c2, 0.f); c3 = fmaxf(c3, 0.f);
            }
            if (res) {
                float2 r0 = *(const float2*)(res + (long)row0 * Nn + col);
                float2 r1 = *(const float2*)(res + (long)(row0 + 8) * Nn + col);
                c0 += r0.x; c1 += r0.y; c2 += r1.x; c3 += r1.y;
            }
            if (Cf) {
                *(float2*)(Cf + (long)row0 * Nn + col) = make_float2(c0, c1);
                *(float2*)(Cf + (long)(row0 + 8) * Nn + col) = make_float2(c2, c3);
            }
            if (Ch) {
                uint32_t h0, l0, h1, l1;
                split2(c0, c1, h0, l0);
                split2(c2, c3, h1, l1);
                *(uint32_t*)(Ch + (long)row0 * Nn + col) = h0;
                *(uint32_t*)(Cl + (long)row0 * Nn + col) = l0;
                *(uint32_t*)(Ch + (long)(row0 + 8) * Nn + col) = h1;
                *(uint32_t*)(Cl + (long)(row0 + 8) * Nn + col) = l1;
            }
            if (do_stats) {
                s[nf * 2 + 0]  += c0 + c2;
                s[nf * 2 + 1]  += c1 + c3;
                q2[nf * 2 + 0] += c0 * c0 + c2 * c2;
                q2[nf * 2 + 1] += c1 * c1 + c3 * c3;
            }
        }
    }
    if (do_stats) {
#pragma unroll
        for (int i = 0; i < 16; i++) {
#pragma unroll
            for (int m = 4; m <= 16; m <<= 1) {
                s[i]  += __shfl_xor_sync(0xffffffffu, s[i],  m);
                q2[i] += __shfl_xor_sync(0xffffffffu, q2[i], m);
            }
        }
        if ((lane >> 2) == 0) {
#pragma unroll
            for (int nf = 0; nf < 8; nf++) {
                int col = n0 + wn + nf * 8 + lane * 2;
                atomicAdd(&g_sum[par][col],     s[nf * 2 + 0]);
                atomicAdd(&g_sum[par][col + 1], s[nf * 2 + 1]);
                atomicAdd(&g_ss[par][col],      q2[nf * 2 + 0]);
                atomicAdd(&g_ss[par][col + 1],  q2[nf * 2 + 1]);
            }
        }
    }
}

// =====================================================================
// non-GEMM kernels
// =====================================================================
__global__ void k_encode(const int* __restrict__ x, const float* __restrict__ pe,
                         const float* __restrict__ atom, const float* __restrict__ pe_w,
                         const float* __restrict__ pe_b) {
    int n = blockIdx.x;
    int d = threadIdx.x * 4;
    __shared__ int   xs[9];
    __shared__ float ps[WW];
    if (threadIdx.x < 9) xs[threadIdx.x] = x[n * 9 + threadIdx.x];
    if (threadIdx.x >= 32 && threadIdx.x < 32 + WW) ps[threadIdx.x - 32] = pe[n * WW + (threadIdx.x - 32)];
    __syncthreads();
    float4 acc = *(const float4*)(pe_b + d);
#pragma unroll
    for (int c = 0; c < 9; c++) {
        float4 v = *(const float4*)(atom + ((long)(c * AV + xs[c]) * DD + d));
        acc.x += v.x; acc.y += v.y; acc.z += v.z; acc.w += v.w;
    }
#pragma unroll
    for (int w = 0; w < WW; w++) {
        float p = ps[w];
        float4 v = *(const float4*)(pe_w + (long)w * DD + d);
        acc.x = fmaf(p, v.x, acc.x); acc.y = fmaf(p, v.y, acc.y);
        acc.z = fmaf(p, v.z, acc.z); acc.w = fmaf(p, v.w, acc.w);
    }
    long o = (long)n * DD + d;
    *(float4*)(g_h + o) = acc;
    uint32_t h0, l0, h1, l1;
    split2(acc.x, acc.y, h0, l0);
    split2(acc.z, acc.w, h1, l1);
    *(uint2*)(g_hsh + o) = make_uint2(h0, h1);
    *(uint2*)(g_hsl + o) = make_uint2(l0, l1);
}

__global__ void k_scatter(const int* __restrict__ ei, const int* __restrict__ eattr,
                          const float* __restrict__ bond) {
    int le = threadIdx.x >> 6;
    int d  = (threadIdx.x & 63) * 4;
    long e = (long)blockIdx.x * 4 + le;
    int src = ei[e];
    int dst = ei[(long)EE + e];
    int a0 = eattr[e * 3 + 0], a1 = eattr[e * 3 + 1], a2 = eattr[e * 3 + 2];
    float4 hv = *(const float4*)(g_h + (long)src * DD + d);
    float4 b0 = *(const float4*)(bond + (long)(0 * BV + a0) * DD + d);
    float4 b1 = *(const float4*)(bond + (long)(1 * BV + a1) * DD + d);
    float4 b2 = *(const float4*)(bond + (long)(2 * BV + a2) * DD + d);
    float m0 = fmaxf(hv.x + b0.x + b1.x + b2.x, 0.f);
    float m1 = fmaxf(hv.y + b0.y + b1.y + b2.y, 0.f);
    float m2 = fmaxf(hv.z + b0.z + b1.z + b2.z, 0.f);
    float m3 = fmaxf(hv.w + b0.w + b1.w + b2.w, 0.f);
    float* zp = g_z + (long)dst * DD + d;
    atomicAdd(zp + 0, m0); atomicAdd(zp + 1, m1);
    atomicAdd(zp + 2, m2); atomicAdd(zp + 3, m3);
}

// BatchNorm apply. Outputs: optional fp32 Ofp, optional split (Oh,Ol).
// Optional post-bn residual add (radd). Zeroes stats[par^1].
__global__ void k_bn(const float* __restrict__ A,
                     const float* __restrict__ gma, const float* __restrict__ bta,
                     float* __restrict__ Ofp,
                     unsigned short* __restrict__ Oh, unsigned short* __restrict__ Ol,
                     const float* __restrict__ radd, int relu, int par) {
    long i = ((long)blockIdx.x * 256 + threadIdx.x) * 2;
    int d = (int)(i & (DD - 1));
    float2 mu2 = *(const float2*)(&g_sum[par][d]);
    float2 ss2 = *(const float2*)(&g_ss[par][d]);
    float2 gm  = *(const float2*)(gma + d);
    float2 bt  = *(const float2*)(bta + d);
    float2 va  = *(const float2*)(A + i);
    float mu0 = mu2.x * (1.f / NN), mu1 = mu2.y * (1.f / NN);
    float v0 = (va.x - mu0) * rsqrtf(ss2.x * (1.f / NN) - mu0 * mu0 + 1e-5f) * gm.x + bt.x;
    float v1 = (va.y - mu1) * rsqrtf(ss2.y * (1.f / NN) - mu1 * mu1 + 1e-5f) * gm.y + bt.y;
    if (relu) { v0 = fmaxf(v0, 0.f); v1 = fmaxf(v1, 0.f); }
    if (radd) {
        float2 r = *(const float2*)(radd + i);
        v0 += r.x; v1 += r.y;
    }
    if (Ofp) *(float2*)(Ofp + i) = make_float2(v0, v1);
    if (Oh) {
        uint32_t h0, l0;
        split2(v0, v1, h0, l0);
        *(uint32_t*)(Oh + i) = h0;
        *(uint32_t*)(Ol + i) = l0;
    }
    if (blockIdx.x == 0 && threadIdx.x < DD / 2) {
        *(float2*)(&g_sum[par ^ 1][threadIdx.x * 2]) = make_float2(0.f, 0.f);
        *(float2*)(&g_ss [par ^ 1][threadIdx.x * 2]) = make_float2(0.f, 0.f);
    }
}

constexpr int ATTN_SMEM = (2 * NPG * 33 + NPG * 129) * 4;
__global__ void k_attention() {
    extern __shared__ float sm[];
    float* Ks = sm;
    float* Vs = Ks + NPG * 33;
    float* Ss = Vs + NPG * 33;
    int head = blockIdx.x, g = blockIdx.y;
    int i = threadIdx.x;
    const float* base = g_qkv + (long)(g * NPG + i) * (3 * DD);

    float q[DHH];
#pragma unroll
    for (int k = 0; k < DHH; k++) {
        q[k] = base[head * DHH + k];
        Ks[i * 33 + k] = base[DD + head * DHH + k];
        Vs[i * 33 + k] = base[2 * DD + head * DHH + k];
    }
    __syncthreads();

    const float scale = 0.17677669529663688f;
    float mx = -1e30f;
#pragma unroll 4
    for (int j = 0; j < NPG; j++) {
        float sv = 0.f;
#pragma unroll
        for (int k = 0; k < DHH; k++) sv = fmaf(q[k], Ks[j * 33 + k], sv);
        sv *= scale;
        Ss[i * 129 + j] = sv;
        mx = fmaxf(mx, sv);
    }
    float denom = 0.f;
#pragma unroll 4
    for (int j = 0; j < NPG; j++) {
        float p = __expf(Ss[i * 129 + j] - mx);
        Ss[i * 129 + j] = p;
        denom += p;
    }
    float inv = 1.f / denom;
    float o[DHH];
#pragma unroll
    for (int k = 0; k < DHH; k++) o[k] = 0.f;
#pragma unroll 4
    for (int j = 0; j < NPG; j++) {
        float p = Ss[i * 129 + j];
#pragma unroll
        for (int k = 0; k < DHH; k++) o[k] = fmaf(p, Vs[j * 33 + k], o[k]);
    }
    // write split bf16 hi/lo (attn only feeds the wo GEMM)
    long ob = (long)(g * NPG + i) * DD + head * DHH;
#pragma unroll
    for (int k = 0; k < DHH; k += 2) {
        uint32_t h0, l0;
        split2(o[k] * inv, o[k + 1] * inv, h0, l0);
        *(uint32_t*)(g_xh + ob + k) = h0;
        *(uint32_t*)(g_xl + ob + k) = l0;
    }
}

__global__ void k_pool(float* __restrict__ out) {
    int g = blockIdx.x, d = threadIdx.x;
    float s = 0.f;
    for (int i = 0; i < NPG; i++) s += g_h[(long)(g * NPG + i) * DD + d];
    out[g * DD + d] = s;
}

// =====================================================================
// host orchestration
// =====================================================================
static void tgemm(const unsigned short* Ah, const unsigned short* Al,
                  const unsigned short* Bh, const unsigned short* Bl,
                  const float* bias, const float* res,
                  float* Cf, unsigned short* Ch, unsigned short* Cl,
                  int Nn, int K, int relu, int do_stats, int par) {
    dim3 grid(Nn / 128, NN / 128);
    k_tgemm<<<grid, 256, SM_TOT>>>(Ah, Al, Bh, Bl, bias, res, Cf, Ch, Cl,
                                   Nn, K, relu, do_stats, par);
}

extern "C" void kernel_launch(void* const* d_in, const int* in_sizes, int n_in,
                              void* d_out, int out_size) {
    const int*   x     = (const int*)d_in[0];
    const int*   ei    = (const int*)d_in[1];
    const int*   eattr = (const int*)d_in[2];
    const float* pe    = (const float*)d_in[4];
    const float* atom  = (const float*)d_in[5];
    const float* bond  = (const float*)d_in[6];
    const float* pe_w  = (const float*)d_in[7];
    const float* pe_b  = (const float*)d_in[8];
    const float* gw1   = (const float*)d_in[9];
    const float* gb1   = (const float*)d_in[10];
    const float* gg1   = (const float*)d_in[11];
    const float* gbe1  = (const float*)d_in[12];
    const float* gw2   = (const float*)d_in[13];
    const float* gb2   = (const float*)d_in[14];
    const float* wqkv  = (const float*)d_in[15];
    const float* bqkv  = (const float*)d_in[16];
    const float* wo    = (const float*)d_in[17];
    const float* bo    = (const float*)d_in[18];
    const float* n1g   = (const float*)d_in[19];
    const float* n1b   = (const float*)d_in[20];
    const float* n2g   = (const float*)d_in[21];
    const float* n2b   = (const float*)d_in[22];
    const float* n3g   = (const float*)d_in[23];
    const float* n3b   = (const float*)d_in[24];
    const float* mw1   = (const float*)d_in[25];
    const float* mb1   = (const float*)d_in[26];
    const float* mw2   = (const float*)d_in[27];
    const float* mb2   = (const float*)d_in[28];

    float *h, *z, *t1, *hl, *qkv;
    unsigned short *wh, *wl, *xh, *xl, *hsh, *hsl, *fsh, *fsl;
    cudaGetSymbolAddress((void**)&h,    g_h);
    cudaGetSymbolAddress((void**)&z,    g_z);
    cudaGetSymbolAddress((void**)&t1,   g_t1);
    cudaGetSymbolAddress((void**)&hl,   g_hl);
    cudaGetSymbolAddress((void**)&qkv,  g_qkv);
    cudaGetSymbolAddress((void**)&wh,   g_wh);
    cudaGetSymbolAddress((void**)&wl,   g_wl);
    cudaGetSymbolAddress((void**)&xh,   g_xh);
    cudaGetSymbolAddress((void**)&xl,   g_xl);
    cudaGetSymbolAddress((void**)&hsh,  g_hsh);
    cudaGetSymbolAddress((void**)&hsl,  g_hsl);
    cudaGetSymbolAddress((void**)&fsh,  g_fsh);
    cudaGetSymbolAddress((void**)&fsl,  g_fsl);

    cudaFuncSetAttribute(k_attention, cudaFuncAttributeMaxDynamicSharedMemorySize, ATTN_SMEM);
    cudaFuncSetAttribute(k_tgemm,     cudaFuncAttributeMaxDynamicSharedMemorySize, SM_TOT);

    const long ND = (long)NN * DD;
    const int BN_BLOCKS = (int)(ND / 512);
    const int CVT_BLOCKS = (int)(ND / 1024);

    // ---- single-launch weight prep + stats zero ----
    k_wprep_all<<<(int)((LL * WL_STRIDE + 255) / 256), 256>>>(gw1, gw2, wqkv, wo, mw1, mw2);

    k_encode<<<NN, 64>>>(x, pe, atom, pe_w, pe_b);   // h fp32 + h split

    for (int l = 0; l < LL; l++) {
        long off = (long)l * WL_STRIDE;
        const unsigned short* W1h = wh + off,           *W1l = wl + off;
        const unsigned short* W2h = wh + off + 65536,   *W2l = wl + off + 65536;
        const unsigned short* Wqh = wh + off + 131072,  *Wql = wl + off + 131072;
        const unsigned short* Woh = wh + off + 327680,  *Wol = wl + off + 327680;
        const unsigned short* M1h = wh + off + 393216,  *M1l = wl + off + 393216;
        const unsigned short* M2h = wh + off + 524288,  *M2l = wl + off + 524288;

        // --- GINEConv ---
        cudaMemcpyAsync(z, h, ND * sizeof(float), cudaMemcpyDeviceToDevice);
        k_scatter<<<EE / 4, 256>>>(ei, eattr, bond);
        k_acvt<<<CVT_BLOCKS, 256>>>(z, xh, xl);                    // z split
        tgemm(xh, xl, W1h, W1l, gb1 + l * DD, nullptr, t1, nullptr, nullptr, DD, DD, 0, 1, 0);
        // t2 = relu(bn(t1)) -> split only
        k_bn<<<BN_BLOCKS, 256>>>(t1, gg1 + l * DD, gbe1 + l * DD, nullptr, xh, xl, nullptr, 1, 0);
        // t1 = relu(t2@w2+b2) + h ; stats par1
        tgemm(xh, xl, W2h, W2l, gb2 + l * DD, h, t1, nullptr, nullptr, DD, DD, 1, 1, 1);
        // hl = bn(t1) fp32
        k_bn<<<BN_BLOCKS, 256>>>(t1, n1g + l * DD, n1b + l * DD, hl, nullptr, nullptr, nullptr, 0, 1);

        // --- attention branch (A = h split, produced at end of prev layer / encode) ---
        tgemm(hsh, hsl, Wqh, Wql, bqkv + l * 3 * DD, nullptr, qkv, nullptr, nullptr, 3 * DD, DD, 0, 0, 0);
        k_attention<<<dim3(HH, GG), NPG, ATTN_SMEM>>>();           // -> (xh, xl) split
        // t1 = attn@wo+bo + h ; stats par0
        tgemm(xh, xl, Woh, Wol, bo + l * DD, h, t1, nullptr, nullptr, DD, DD, 0, 1, 0);
        // comb = hl + bn(t1) -> split only
        k_bn<<<BN_BLOCKS, 256>>>(t1, n2g + l * DD, n2b + l * DD, nullptr, xh, xl, hl, 0, 0);

        // --- MLP: ff = relu(comb@mw1+mb1) -> split direct from epilogue ---
        tgemm(xh, xl, M1h, M1l, mb1 + l * FF, nullptr, nullptr, fsh, fsl, FF, DD, 1, 0, 0);
        // t1 = ff@mw2+mb2 ; stats par1
        tgemm(fsh, fsl, M2h, M2l, mb2 + l * DD, nullptr, t1, nullptr, nullptr, DD, FF, 0, 1, 1);
        // h = bn(t1) fp32 + split (for next layer qkv)
        k_bn<<<BN_BLOCKS, 256>>>(t1, n3g + l * DD, n3b + l * DD, h, hsh, hsl, nullptr, 0, 1);
    }

    k_pool<<<GG, DD>>>((float*)d_out);
}